// round 7
// baseline (speedup 1.0000x reference)
#include <cuda_runtime.h>
#include <cuda_bf16.h>
#include <math.h>

// Problem constants
#define BZ   128
#define T_   32
#define D_   768
#define DFF_ 3072
#define E_   8
#define BEAMS_ 2
#define NROWS (BZ * BEAMS_)                    // 256
#define OUT_ELEMS ((size_t)NROWS * T_ * D_)    // 6,291,456

// Scratch
__device__ __align__(256) float g_h[(size_t)NROWS * T_ * DFF_];       // 100.7 MB (tf32-rounded)
__device__ __align__(256) float g_xr[(size_t)BZ * T_ * D_];           // 12.6 MB (tf32-rounded x)
__device__ __align__(256) float g_w1t[(size_t)E_ * DFF_ * D_];        // 75.5 MB W1^T [e][f][d]
__device__ __align__(256) float g_w2t[(size_t)E_ * D_ * DFF_];        // 75.5 MB W2^T [e][d][f]
// Routing state
__device__ int g_sel[NROWS];
__device__ int g_cnt[E_];
__device__ int g_rows[E_][NROWS];

__device__ __forceinline__ unsigned f2tf(float f) {
    unsigned u;
    asm("cvt.rna.tf32.f32 %0, %1;" : "=r"(u) : "f"(f));
    return u;
}

// ---------------------------------------------------------------------------
// Gating: mean-pool over T, logits = avg @ Wg, softmax, top-2 (stable ties)
// ---------------------------------------------------------------------------
__global__ void gate_kernel(const float* __restrict__ x,
                            const float* __restrict__ Wg,
                            float* __restrict__ out, int out_size)
{
    const int b = blockIdx.x;
    const int t = threadIdx.x;
    __shared__ float s_avg[D_];
    __shared__ float s_logits[E_];

    const float* xb = x + (size_t)b * T_ * D_;
    for (int d = t; d < D_; d += 256) {
        float s = 0.f;
        #pragma unroll
        for (int tt = 0; tt < T_; tt++) s += xb[tt * D_ + d];
        s_avg[d] = s * (1.0f / (float)T_);
    }
    __syncthreads();

    const int w = t >> 5, lane = t & 31;
    float p = 0.f;
    for (int d = lane; d < D_; d += 32) p += s_avg[d] * Wg[d * E_ + w];
    #pragma unroll
    for (int o = 16; o; o >>= 1) p += __shfl_xor_sync(0xffffffffu, p, o);
    if (lane == 0) s_logits[w] = p;
    __syncthreads();

    if (t == 0) {
        float mx = s_logits[0];
        #pragma unroll
        for (int e = 1; e < E_; e++) mx = fmaxf(mx, s_logits[e]);
        float pr[E_]; float se = 0.f;
        #pragma unroll
        for (int e = 0; e < E_; e++) { pr[e] = expf(s_logits[e] - mx); se += pr[e]; }
        float inv = 1.0f / se;
        #pragma unroll
        for (int e = 0; e < E_; e++) pr[e] *= inv;

        int i1 = 0;
        #pragma unroll
        for (int e = 1; e < E_; e++) if (pr[e] > pr[i1]) i1 = e;
        int i2 = -1;
        #pragma unroll
        for (int e = 0; e < E_; e++) {
            if (e == i1) continue;
            if (i2 < 0 || pr[e] > pr[i2]) i2 = e;
        }

        g_sel[2 * b + 0] = i1;
        g_sel[2 * b + 1] = i2;

        if (out_size >= (int)(OUT_ELEMS + 2 * NROWS)) {
            out[OUT_ELEMS + 2 * b + 0] = pr[i1];
            out[OUT_ELEMS + 2 * b + 1] = pr[i2];
            out[OUT_ELEMS + NROWS + 2 * b + 0] = (float)i1;
            out[OUT_ELEMS + NROWS + 2 * b + 1] = (float)i2;
        }
    }
}

__global__ void route_build_kernel()
{
    if (threadIdx.x == 0 && blockIdx.x == 0) {
        int cnt[E_];
        #pragma unroll
        for (int e = 0; e < E_; e++) cnt[e] = 0;
        for (int n = 0; n < NROWS; n++) {
            int e = g_sel[n];
            g_rows[e][cnt[e]++] = n;
        }
        #pragma unroll
        for (int e = 0; e < E_; e++) g_cnt[e] = cnt[e];
    }
}

// ---------------------------------------------------------------------------
// Prep: round x to tf32; transpose+round W -> W^T [e][n][k] (k contiguous)
// ---------------------------------------------------------------------------
__global__ void round_x_kernel(const float* __restrict__ x)
{
    int idx = blockIdx.x * 256 + threadIdx.x;          // float4 index
    float4 v = ((const float4*)x)[idx];
    uint4 u = make_uint4(f2tf(v.x), f2tf(v.y), f2tf(v.z), f2tf(v.w));
    ((uint4*)g_xr)[idx] = u;
}

template <int R, int C>
__global__ void transpose_cvt_kernel(const float* __restrict__ in,
                                     float* __restrict__ outp)
{
    __shared__ float tile[32][33];
    const int e  = blockIdx.z;
    const int c0 = blockIdx.x * 32;
    const int r0 = blockIdx.y * 32;
    const int tx = threadIdx.x;      // 0..31
    const int ty = threadIdx.y;      // 0..7

    const float* src = in + ((size_t)e * R + r0) * C + c0;
    #pragma unroll
    for (int i = 0; i < 4; i++)
        tile[ty + i * 8][tx] = src[(size_t)(ty + i * 8) * C + tx];
    __syncthreads();

    float* dst = outp + ((size_t)e * C + c0) * R + r0;
    #pragma unroll
    for (int i = 0; i < 4; i++)
        dst[(size_t)(ty + i * 8) * R + tx] =
            __uint_as_float(f2tf(tile[tx][ty + i * 8]));
}

// ---------------------------------------------------------------------------
// TF32 grouped GEMM: 128x128 block tile, 8 warps (4m x 2n), warp tile 32x64.
// Operands pre-rounded to tf32 => ZERO cvt in kernel.
// cp.async 3-stage ring; A smem [m][k], B smem [n][k] (both 128B rows,
// XOR swizzle granule ^= row&7); ldmatrix.x4 fragment loads (validated R5).
// ---------------------------------------------------------------------------
#define STAGE_BYTES 16384                         // 128 rows * 128 B
#define NSTAGES     3
#define A_BASE      0
#define B_BASE      (NSTAGES * STAGE_BYTES)
#define SMEM_BYTES  (2 * NSTAGES * STAGE_BYTES)   // 98304

__device__ __forceinline__ void mma_tf32(float* c, const unsigned* a, const unsigned* b) {
    asm volatile(
        "mma.sync.aligned.m16n8k8.row.col.f32.tf32.tf32.f32 "
        "{%0,%1,%2,%3}, {%4,%5,%6,%7}, {%8,%9}, {%0,%1,%2,%3};"
        : "+f"(c[0]), "+f"(c[1]), "+f"(c[2]), "+f"(c[3])
        : "r"(a[0]), "r"(a[1]), "r"(a[2]), "r"(a[3]), "r"(b[0]), "r"(b[1]));
}

__device__ __forceinline__ void ldsm_x4(unsigned& r0, unsigned& r1,
                                        unsigned& r2, unsigned& r3, unsigned addr) {
    asm volatile("ldmatrix.sync.aligned.m8n8.x4.shared.b16 {%0,%1,%2,%3}, [%4];"
                 : "=r"(r0), "=r"(r1), "=r"(r2), "=r"(r3) : "r"(addr));
}

__device__ __forceinline__ void cp_async16(unsigned smem_dst, const float* gmem_src) {
    asm volatile("cp.async.cg.shared.global [%0], [%1], 16;\n"
                 :: "r"(smem_dst), "l"(gmem_src));
}
__device__ __forceinline__ void cp_commit() {
    asm volatile("cp.async.commit_group;\n");
}
template <int N>
__device__ __forceinline__ void cp_wait() {
    asm volatile("cp.async.wait_group %0;\n" :: "n"(N));
}

__device__ __forceinline__ float gelu_exact(float v) {
    return 0.5f * v * (1.0f + erff(v * 0.70710678118654752f));
}

template <int KDIM, int NDIM, bool GELU, bool HALF_IN, bool OUT_GH, bool IN_GH>
__global__ __launch_bounds__(256, 2)
void moe_gemm(const float* __restrict__ Wt,     // [E][NDIM][KDIM] tf32-rounded
              const float* __restrict__ Bbase,  // bias [E][NDIM] fp32
              float* __restrict__ Oarg)
{
    const int e     = blockIdx.z;
    const int cnt   = g_cnt[e];
    const int mtile = blockIdx.y;
    if (mtile * 4 >= cnt) return;
    const int ntile = blockIdx.x;

    extern __shared__ char smem_raw[];
    const unsigned smem_u32 = (unsigned)__cvta_generic_to_shared(smem_raw);
    __shared__ int s_rows[4];

    const int t = threadIdx.x;      // 0..255
    if (t < 4) {
        int idx = mtile * 4 + t;
        s_rows[t] = (idx < cnt) ? g_rows[e][idx] : -1;
    }
    __syncthreads();

    const float* A0   = IN_GH ? g_h : g_xr;
    const float* bias = Bbase + (size_t)e * NDIM + ntile * 128;

    const int warp = t >> 5, lane = t & 31;
    const int wm = (warp & 3) * 32;          // 4 warps along m
    const int wn = (warp >> 2) * 64;         // 2 warps along n

    float acc[2][8][4];
    #pragma unroll
    for (int i = 0; i < 2; i++)
        #pragma unroll
        for (int j = 0; j < 8; j++)
            #pragma unroll
            for (int q = 0; q < 4; q++) acc[i][j][q] = 0.f;

    // ---- cp.async addressing: idx = t + g*256 -> (row = idx>>3, kq = idx&7)
    const float* a_src[4];
    const float* b_src[4];
    unsigned a_sts[4], b_sts[4];
    #pragma unroll
    for (int g = 0; g < 4; g++) {
        int idx = t + g * 256;
        int row = idx >> 3;                  // 0..127
        int kq  = idx & 7;
        // A: gathered token rows
        int r = s_rows[row >> 5];
        if (r < 0) r = s_rows[0];
        int arow = HALF_IN ? (r >> 1) : r;
        a_src[g] = A0 + ((size_t)arow * T_ + (row & 31)) * (size_t)KDIM + kq * 4;
        a_sts[g] = row * 128 + ((kq ^ (row & 7)) << 4);
        // B: W^T rows (n-major, k contiguous)
        b_src[g] = Wt + ((size_t)e * NDIM + (size_t)ntile * 128 + row) * (size_t)KDIM + kq * 4;
        b_sts[g] = row * 128 + ((kq ^ (row & 7)) << 4);
    }

    // ---- ldmatrix fragment addressing (validated in R5) ------------------
    const int rin     = lane & 7;
    const int amrow0  = wm + (((lane >> 3) & 1) << 3) + rin;
    const int a_row_b = amrow0 * 128;
    const int a_gbit  = lane >> 4;
    const int bnrow0  = wn + ((lane >> 4) << 3) + rin;
    const int b_row_b = bnrow0 * 128;
    const int b_gbit  = (lane >> 3) & 1;

    const int iters = KDIM / 32;

    auto load_stage = [&](int s, int slot) {
        const int k0 = s * 32;
        const unsigned Ad = smem_u32 + A_BASE + slot * STAGE_BYTES;
        const unsigned Bd = smem_u32 + B_BASE + slot * STAGE_BYTES;
        #pragma unroll
        for (int g = 0; g < 4; g++) cp_async16(Ad + a_sts[g], a_src[g] + k0);
        #pragma unroll
        for (int g = 0; g < 4; g++) cp_async16(Bd + b_sts[g], b_src[g] + k0);
    };

    // Prologue: stages 0,1 in flight
    load_stage(0, 0); cp_commit();
    if (iters > 1) { load_stage(1, 1); }
    cp_commit();

    int slot = 0;
    for (int it = 0; it < iters; it++) {
        cp_wait<1>();
        __syncthreads();

        // issue stage it+2 (into slot (it+2)%3 == slot-1, safe post-barrier)
        if (it + 2 < iters) {
            int ns = it + 2 - ((it + 2) / NSTAGES) * NSTAGES;
            load_stage(it + 2, ns);
        }
        cp_commit();

        const unsigned Au = smem_u32 + A_BASE + slot * STAGE_BYTES;
        const unsigned Bu = smem_u32 + B_BASE + slot * STAGE_BYTES;

        #pragma unroll
        for (int ks = 0; ks < 4; ks++) {
            unsigned a[2][4], b[8][2];
            {
                int gA = 2 * ks + a_gbit;
                unsigned off0 = Au + a_row_b + ((gA ^ rin) << 4);
                ldsm_x4(a[0][0], a[0][1], a[0][2], a[0][3], off0);
                ldsm_x4(a[1][0], a[1][1], a[1][2], a[1][3], off0 + 16 * 128);
            }
            {
                int gB = 2 * ks + b_gbit;
                unsigned base = Bu + b_row_b + ((gB ^ rin) << 4);
                #pragma unroll
                for (int jj = 0; jj < 4; jj++) {
                    ldsm_x4(b[2 * jj][0], b[2 * jj][1],
                            b[2 * jj + 1][0], b[2 * jj + 1][1],
                            base + jj * (16 * 128));
                }
            }
            #pragma unroll
            for (int i = 0; i < 2; i++)
                #pragma unroll
                for (int j = 0; j < 8; j++)
                    mma_tf32(acc[i][j], a[i], b[j]);
        }
        slot = (slot + 1 == NSTAGES) ? 0 : slot + 1;
    }

    // --- epilogue: bias (+GELU), scatter; GEMM1 output stored tf32-rounded
    #pragma unroll
    for (int i = 0; i < 2; i++) {
        int r0 = wm + i * 16 + (lane >> 2);
        #pragma unroll
        for (int half = 0; half < 2; half++) {
            int gm   = r0 + half * 8;
            int grow = s_rows[gm >> 5];
            if (grow < 0) continue;
            float* orow = (OUT_GH ? g_h : Oarg)
                        + ((size_t)grow * T_ + (gm & 31)) * (size_t)NDIM
                        + (size_t)ntile * 128;
            #pragma unroll
            for (int j = 0; j < 8; j++) {
                int c0 = wn + j * 8 + 2 * (lane & 3);
                float v0 = acc[i][j][half * 2 + 0] + bias[c0];
                float v1 = acc[i][j][half * 2 + 1] + bias[c0 + 1];
                if (GELU) { v0 = gelu_exact(v0); v1 = gelu_exact(v1); }
                if (OUT_GH) {
                    orow[c0]     = __uint_as_float(f2tf(v0));
                    orow[c0 + 1] = __uint_as_float(f2tf(v1));
                } else {
                    orow[c0]     = v0;
                    orow[c0 + 1] = v1;
                }
            }
        }
    }
}

// ---------------------------------------------------------------------------
// Launch
// ---------------------------------------------------------------------------
extern "C" void kernel_launch(void* const* d_in, const int* in_sizes, int n_in,
                              void* d_out, int out_size)
{
    const float* x  = (const float*)d_in[0];
    const float* Wg = (const float*)d_in[2];
    const float* W1 = (const float*)d_in[3];
    const float* b1 = (const float*)d_in[4];
    const float* W2 = (const float*)d_in[5];
    const float* b2 = (const float*)d_in[6];
    float* out = (float*)d_out;

    cudaFuncSetAttribute(moe_gemm<D_, DFF_, true, true, true, false>,
                         cudaFuncAttributeMaxDynamicSharedMemorySize, SMEM_BYTES);
    cudaFuncSetAttribute(moe_gemm<DFF_, D_, false, false, false, true>,
                         cudaFuncAttributeMaxDynamicSharedMemorySize, SMEM_BYTES);

    // 1) Gating + routing (+ prep in parallel conceptually; stream-serial is fine)
    gate_kernel<<<BZ, 256>>>(x, Wg, out, out_size);
    route_build_kernel<<<1, 32>>>();

    // 2) Pre-round x, transpose+round W1 and W2
    round_x_kernel<<<(BZ * T_ * D_) / (256 * 4), 256>>>(x);
    transpose_cvt_kernel<D_, DFF_><<<dim3(DFF_ / 32, D_ / 32, E_), dim3(32, 8)>>>(W1, g_w1t);
    transpose_cvt_kernel<DFF_, D_><<<dim3(D_ / 32, DFF_ / 32, E_), dim3(32, 8)>>>(W2, g_w2t);

    // 3) h = gelu(x[n/2] @ W1[sel] + b1[sel])  (grouped by expert)
    moe_gemm<D_, DFF_, true, true, true, false>
        <<<dim3(DFF_ / 128, 64, E_), 256, SMEM_BYTES>>>(g_w1t, b1, out);

    // 4) out = h @ W2[sel] + b2[sel]
    moe_gemm<DFF_, D_, false, false, false, true>
        <<<dim3(D_ / 128, 64, E_), 256, SMEM_BYTES>>>(g_w2t, b2, out);
}

// round 10
// speedup vs baseline: 22.4861x; 22.4861x over previous
#include <cuda_runtime.h>
#include <cuda_bf16.h>
#include <math.h>

// Problem constants
#define BZ   128
#define T_   32
#define D_   768
#define DFF_ 3072
#define E_   8
#define BEAMS_ 2
#define NROWS (BZ * BEAMS_)                    // 256
#define OUT_ELEMS ((size_t)NROWS * T_ * D_)    // 6,291,456

// Scratch: h = gelu(x @ W1 + b1), stored tf32-rounded (bit pattern in fp32)
__device__ __align__(256) float g_h[(size_t)NROWS * T_ * DFF_];
// x pre-rounded to tf32 (12.6 MB)
__device__ __align__(256) float g_xr[(size_t)BZ * T_ * D_];
// Routing state
__device__ int g_sel[NROWS];
__device__ int g_cnt[E_];
__device__ int g_rows[E_][NROWS];

__device__ __forceinline__ unsigned f2tf(float f) {
    unsigned u;
    asm("cvt.rna.tf32.f32 %0, %1;" : "=r"(u) : "f"(f));
    return u;
}

// ---------------------------------------------------------------------------
// Gating: mean-pool over T, logits = avg @ Wg, softmax, top-2 (stable ties)
// ---------------------------------------------------------------------------
__global__ void gate_kernel(const float* __restrict__ x,
                            const float* __restrict__ Wg,
                            float* __restrict__ out, int out_size)
{
    const int b = blockIdx.x;
    const int t = threadIdx.x;
    __shared__ float s_avg[D_];
    __shared__ float s_logits[E_];

    const float* xb = x + (size_t)b * T_ * D_;
    for (int d = t; d < D_; d += 256) {
        float s = 0.f;
        #pragma unroll
        for (int tt = 0; tt < T_; tt++) s += xb[tt * D_ + d];
        s_avg[d] = s * (1.0f / (float)T_);
    }
    __syncthreads();

    const int w = t >> 5, lane = t & 31;
    float p = 0.f;
    for (int d = lane; d < D_; d += 32) p += s_avg[d] * Wg[d * E_ + w];
    #pragma unroll
    for (int o = 16; o; o >>= 1) p += __shfl_xor_sync(0xffffffffu, p, o);
    if (lane == 0) s_logits[w] = p;
    __syncthreads();

    if (t == 0) {
        float mx = s_logits[0];
        #pragma unroll
        for (int e = 1; e < E_; e++) mx = fmaxf(mx, s_logits[e]);
        float pr[E_]; float se = 0.f;
        #pragma unroll
        for (int e = 0; e < E_; e++) { pr[e] = expf(s_logits[e] - mx); se += pr[e]; }
        float inv = 1.0f / se;
        #pragma unroll
        for (int e = 0; e < E_; e++) pr[e] *= inv;

        int i1 = 0;
        #pragma unroll
        for (int e = 1; e < E_; e++) if (pr[e] > pr[i1]) i1 = e;
        int i2 = -1;
        #pragma unroll
        for (int e = 0; e < E_; e++) {
            if (e == i1) continue;
            if (i2 < 0 || pr[e] > pr[i2]) i2 = e;
        }

        g_sel[2 * b + 0] = i1;
        g_sel[2 * b + 1] = i2;

        if (out_size >= (int)(OUT_ELEMS + 2 * NROWS)) {
            out[OUT_ELEMS + 2 * b + 0] = pr[i1];
            out[OUT_ELEMS + 2 * b + 1] = pr[i2];
            out[OUT_ELEMS + NROWS + 2 * b + 0] = (float)i1;
            out[OUT_ELEMS + NROWS + 2 * b + 1] = (float)i2;
        }
    }
}

__global__ void route_build_kernel()
{
    if (threadIdx.x == 0 && blockIdx.x == 0) {
        int cnt[E_];
        #pragma unroll
        for (int e = 0; e < E_; e++) cnt[e] = 0;
        for (int n = 0; n < NROWS; n++) {
            int e = g_sel[n];
            g_rows[e][cnt[e]++] = n;
        }
        #pragma unroll
        for (int e = 0; e < E_; e++) g_cnt[e] = cnt[e];
    }
}

// Pre-round x to tf32 (flat coalesced float4 copy, ~8us)
__global__ void round_x_kernel(const float* __restrict__ x)
{
    int idx = blockIdx.x * 256 + threadIdx.x;          // float4 index
    float4 v = ((const float4*)x)[idx];
    uint4 u = make_uint4(f2tf(v.x), f2tf(v.y), f2tf(v.z), f2tf(v.w));
    ((uint4*)g_xr)[idx] = u;
}

// ---------------------------------------------------------------------------
// TF32 tensor-core grouped GEMM, cp.async 3-stage ring, 8 warps/block.
// Per block: 128x128 tile of O = act(A @ W[e] + b[e]) for expert e.
// 256 threads = 8 warps in a 4(m) x 2(n) grid; warp tile 32x64 (m16n8k8).
// A operand pre-rounded tf32 (no cvt); B (weights) cvt at fragment load
// exactly as the 647us champion -> numerics bit-identical.
// ---------------------------------------------------------------------------
#define A_STRIDE 36     // floats per A row in smem (16B aligned, frag conflict-free)
#define B_STRIDE 136    // floats per B k-row in smem (16B aligned, frag conflict-free)
#define A_STAGE  (128 * A_STRIDE)                    // 4608 floats
#define B_STAGE  (32 * B_STRIDE)                     // 4352 floats
#define NSTAGES  3
#define SMEM_FLOATS (NSTAGES * (A_STAGE + B_STAGE))
#define SMEM_BYTES  (SMEM_FLOATS * 4)                // 107,520 B

__device__ __forceinline__ void mma_tf32(float* c, const unsigned* a, const unsigned* b) {
    asm volatile(
        "mma.sync.aligned.m16n8k8.row.col.f32.tf32.tf32.f32 "
        "{%0,%1,%2,%3}, {%4,%5,%6,%7}, {%8,%9}, {%0,%1,%2,%3};"
        : "+f"(c[0]), "+f"(c[1]), "+f"(c[2]), "+f"(c[3])
        : "r"(a[0]), "r"(a[1]), "r"(a[2]), "r"(a[3]), "r"(b[0]), "r"(b[1]));
}

__device__ __forceinline__ void cp_async16(float* smem_dst, const float* gmem_src) {
    unsigned s = (unsigned)__cvta_generic_to_shared(smem_dst);
    asm volatile("cp.async.cg.shared.global [%0], [%1], 16;\n" :: "r"(s), "l"(gmem_src));
}
__device__ __forceinline__ void cp_commit() {
    asm volatile("cp.async.commit_group;\n");
}
template <int N>
__device__ __forceinline__ void cp_wait() {
    asm volatile("cp.async.wait_group %0;\n" :: "n"(N));
}

__device__ __forceinline__ float gelu_exact(float v) {
    return 0.5f * v * (1.0f + erff(v * 0.70710678118654752f));
}

template <int KDIM, int NDIM, bool GELU, bool HALF_IN, bool OUT_GH, bool IN_GH>
__global__ __launch_bounds__(256, 2)
void moe_gemm(const float* __restrict__ Wbase,
              const float* __restrict__ Bbase,
              float* __restrict__ Oarg)
{
    const int e     = blockIdx.z;
    const int cnt   = g_cnt[e];
    const int mtile = blockIdx.y;
    if (mtile * 4 >= cnt) return;
    const int ntile = blockIdx.x;

    extern __shared__ float sm[];
    float* As = sm;                          // [NSTAGES][128][A_STRIDE]
    float* Bs = sm + NSTAGES * A_STAGE;      // [NSTAGES][32][B_STRIDE]
    __shared__ int s_rows[4];

    const int t = threadIdx.x;      // 0..255
    if (t < 4) {
        int idx = mtile * 4 + t;
        s_rows[t] = (idx < cnt) ? g_rows[e][idx] : -1;
    }
    __syncthreads();

    const float* A0   = IN_GH ? g_h : g_xr;   // both pre-rounded tf32
    const float* W    = Wbase + (size_t)e * KDIM * NDIM + (size_t)ntile * 128;
    const float* bias = Bbase + (size_t)e * NDIM + ntile * 128;

    const int warp = t >> 5, lane = t & 31;
    const int wm = (warp & 3) * 32;         // 4 warps along m
    const int wn = (warp >> 2) * 64;        // 2 warps along n

    float acc[2][8][4];
    #pragma unroll
    for (int i = 0; i < 2; i++)
        #pragma unroll
        for (int j = 0; j < 8; j++)
            #pragma unroll
            for (int q = 0; q < 4; q++) acc[i][j][q] = 0.f;

    // Per-thread cp.async chunks: A tile 128x32 -> 1024 16B chunks, 4/thread.
    const float* a_src[4];
    int a_dst[4];
    #pragma unroll
    for (int i = 0; i < 4; i++) {
        int lin = t + i * 256;
        int m   = lin >> 3;
        int kq  = lin & 7;
        int r   = s_rows[m >> 5];
        if (r < 0) r = s_rows[0];
        int arow = HALF_IN ? (r >> 1) : r;
        a_src[i] = A0 + ((size_t)arow * T_ + (m & 31)) * (size_t)KDIM + kq * 4;
        a_dst[i] = m * A_STRIDE + kq * 4;
    }
    // B tile 32x128 -> 1024 chunks, 4/thread.
    const float* b_src[4];
    int b_dst[4];
    #pragma unroll
    for (int i = 0; i < 4; i++) {
        int lin = t + i * 256;
        int kk  = lin >> 5;
        int jq  = lin & 31;
        b_src[i] = W + (size_t)kk * NDIM + jq * 4;
        b_dst[i] = kk * B_STRIDE + jq * 4;
    }

    const int iters = KDIM / 32;

    auto load_stage = [&](int s, int slot) {
        const int k0 = s * 32;
        float* Ad = As + slot * A_STAGE;
        float* Bd = Bs + slot * B_STAGE;
        size_t boff = (size_t)k0 * NDIM;
        #pragma unroll
        for (int i = 0; i < 4; i++) cp_async16(Ad + a_dst[i], a_src[i] + k0);
        #pragma unroll
        for (int i = 0; i < 4; i++) cp_async16(Bd + b_dst[i], b_src[i] + boff);
    };

    // Prologue: stages 0 and 1 in flight
    load_stage(0, 0); cp_commit();
    if (iters > 1) load_stage(1, 1);
    cp_commit();

    const int ar = lane >> 2, ac = lane & 3;

    int slot = 0;
    for (int it = 0; it < iters; it++) {
        cp_wait<1>();        // stage `it` resident (stage it+1 may be in flight)
        __syncthreads();     // all warps see stage `it`; prev compute done

        // Issue stage it+2 into slot (slot+2)%3 (distinct from current & next)
        if (it + 2 < iters) {
            int ns = slot + 2; if (ns >= NSTAGES) ns -= NSTAGES;
            load_stage(it + 2, ns);
        }
        cp_commit();

        const float* Ab = As + slot * A_STAGE;
        const float* Bb = Bs + slot * B_STAGE;

        #pragma unroll
        for (int ks = 0; ks < 4; ks++) {
            const int kb = ks * 8;
            unsigned a[2][4], b[8][2];
            #pragma unroll
            for (int i = 0; i < 2; i++) {
                int row = wm + i * 16 + ar;
                a[i][0] = __float_as_uint(Ab[row * A_STRIDE + kb + ac]);
                a[i][1] = __float_as_uint(Ab[(row + 8) * A_STRIDE + kb + ac]);
                a[i][2] = __float_as_uint(Ab[row * A_STRIDE + kb + ac + 4]);
                a[i][3] = __float_as_uint(Ab[(row + 8) * A_STRIDE + kb + ac + 4]);
            }
            #pragma unroll
            for (int j = 0; j < 8; j++) {
                int col = wn + j * 8 + (lane >> 2);
                b[j][0] = f2tf(Bb[(kb + ac) * B_STRIDE + col]);
                b[j][1] = f2tf(Bb[(kb + ac + 4) * B_STRIDE + col]);
            }
            #pragma unroll
            for (int i = 0; i < 2; i++)
                #pragma unroll
                for (int j = 0; j < 8; j++)
                    mma_tf32(acc[i][j], a[i], b[j]);
        }
        slot = (slot + 1 == NSTAGES) ? 0 : slot + 1;
    }

    // --- epilogue: bias (+GELU), scatter to gathered output rows ---
    // GEMM1 (OUT_GH) stores h pre-rounded to tf32 (same value GEMM2 would
    // have produced with cvt at fragment load -> numerics unchanged).
    #pragma unroll
    for (int i = 0; i < 2; i++) {
        int r0 = wm + i * 16 + (lane >> 2);
        #pragma unroll
        for (int half = 0; half < 2; half++) {
            int gm   = r0 + half * 8;
            int grow = s_rows[gm >> 5];
            if (grow < 0) continue;
            float* orow = (OUT_GH ? g_h : Oarg)
                        + ((size_t)grow * T_ + (gm & 31)) * (size_t)NDIM
                        + (size_t)ntile * 128;
            #pragma unroll
            for (int j = 0; j < 8; j++) {
                int c0 = wn + j * 8 + 2 * (lane & 3);
                float v0 = acc[i][j][half * 2 + 0] + bias[c0];
                float v1 = acc[i][j][half * 2 + 1] + bias[c0 + 1];
                if (GELU) { v0 = gelu_exact(v0); v1 = gelu_exact(v1); }
                if (OUT_GH) {
                    orow[c0]     = __uint_as_float(f2tf(v0));
                    orow[c0 + 1] = __uint_as_float(f2tf(v1));
                } else {
                    orow[c0]     = v0;
                    orow[c0 + 1] = v1;
                }
            }
        }
    }
}

// ---------------------------------------------------------------------------
// Launch
// ---------------------------------------------------------------------------
extern "C" void kernel_launch(void* const* d_in, const int* in_sizes, int n_in,
                              void* d_out, int out_size)
{
    const float* x  = (const float*)d_in[0];
    const float* Wg = (const float*)d_in[2];
    const float* W1 = (const float*)d_in[3];
    const float* b1 = (const float*)d_in[4];
    const float* W2 = (const float*)d_in[5];
    const float* b2 = (const float*)d_in[6];
    float* out = (float*)d_out;

    cudaFuncSetAttribute(moe_gemm<D_, DFF_, true, true, true, false>,
                         cudaFuncAttributeMaxDynamicSharedMemorySize, SMEM_BYTES);
    cudaFuncSetAttribute(moe_gemm<DFF_, D_, false, false, false, true>,
                         cudaFuncAttributeMaxDynamicSharedMemorySize, SMEM_BYTES);

    // 1) Gating + routing + x pre-round (all tiny)
    gate_kernel<<<BZ, 256>>>(x, Wg, out, out_size);
    route_build_kernel<<<1, 32>>>();
    round_x_kernel<<<(BZ * T_ * D_) / (256 * 4), 256>>>(x);

    // 2) h = gelu(x[n/2] @ W1[sel] + b1[sel])  (grouped by expert)
    moe_gemm<D_, DFF_, true, true, true, false>
        <<<dim3(DFF_ / 128, 64, E_), 256, SMEM_BYTES>>>(W1, b1, out);

    // 3) out = h @ W2[sel] + b2[sel]
    moe_gemm<DFF_, D_, false, false, false, true>
        <<<dim3(D_ / 128, 64, E_), 256, SMEM_BYTES>>>(W2, b2, out);
}